// round 8
// baseline (speedup 1.0000x reference)
#include <cuda_runtime.h>
#include <cuda_bf16.h>

// ---------------------------------------------------------------------------
// FlattenedWindowMapping (outputs compared as float32)
// Layout: concat [flat2win[n_p] | win2flat[n] | idx_x[n] | idx_y[n]]
//
// Counting sort over (flag, batch, window) buckets (2^19 bins):
//   bucket = flag<<18 | b<<14 | wcx<<8 | wcy<<2 | wcz   (x-orientation)
//            flag<<18 | b<<14 | wcy<<8 | wcx<<2 | wcz   (y-orientation)
//   element = ciw<<21 | i        (ciw 11 bits, i < 2^21)
// then per-window stable micro-sort by (ciw, i)  == reference key order.
//
// Scan = hang-proof two-level: S1 per-tile local scan (+ inline hist zeroing
// for graph replay), S2 single-block scan of 256 tile totals; tile base added
// at use sites. No inter-block spin waits anywhere.
// ---------------------------------------------------------------------------

#define MAXB  16
#define NMAX  2000000            // < 2^21 for packing
#define NMAX2 (2 * NMAX)
#define NBINS (1 << 19)
#define GROUPSZ 128

#define SCAN_BLOCK 256
#define SCAN_ITEMS 8
#define SCAN_TILE  (SCAN_BLOCK * SCAN_ITEMS)      // 2048
#define NTILES     (NBINS / SCAN_TILE)            // 256
#define TILE_SHIFT 11                             // log2(SCAN_TILE)

__device__ int g_nb;
__device__ int g_bs[MAXB + 1];
__device__ int g_num[MAXB];
__device__ int g_nump[MAXB];
__device__ int g_bsp[MAXB + 1];
__device__ int g_bias[MAXB];

__device__ __align__(16) unsigned int g_hist[NBINS];
__device__ __align__(16) unsigned int g_offs[NBINS];     // local (per-tile) offsets
__device__ unsigned int g_tilesum[NTILES];
__device__ unsigned int g_tilebase[NTILES];
__device__ unsigned int g_binned[NMAX2];

// --- Kernel A: per-batch boundaries via binary search (proven-good) ---------
__global__ void batch_setup_kernel(const int* __restrict__ coords, int n,
                                   const int* __restrict__ bsz_ptr) {
    __shared__ int nb_s;
    int t = threadIdx.x;
    if (t == 0) {
        int nb = bsz_ptr ? bsz_ptr[0] : 16;
        if (nb < 1) nb = 1;
        if (nb > MAXB) nb = MAXB;
        nb_s = nb;
        g_nb = nb;
    }
    __syncthreads();
    int nb = nb_s;
    if (t <= nb) {
        int lo = 0, hi = n;
        while (lo < hi) {
            int mid = (lo + hi) >> 1;
            if (coords[4 * mid] < t) lo = mid + 1; else hi = mid;
        }
        g_bs[t] = lo;
    }
    __syncthreads();
    if (t == 0) {
        int acc = 0;
        for (int b = 0; b < nb; b++) {
            int num  = g_bs[b + 1] - g_bs[b];
            int nump = ((num + GROUPSZ - 1) / GROUPSZ) * GROUPSZ;
            g_num[b]  = num;
            g_nump[b] = nump;
            g_bsp[b]  = acc;
            g_bias[b] = acc - g_bs[b];
            acc += nump;
        }
        g_bsp[nb] = acc;
    }
}

// --- Kernel B: win2flat + bucket histogram (hist zeroed by prior S1/init) ---
__global__ void map_hist_kernel(const int* __restrict__ coords, int n,
                                float* __restrict__ win2flat) {
    int i = blockIdx.x * blockDim.x + threadIdx.x;
    if (i >= n) return;

    int4 c = reinterpret_cast<const int4*>(coords)[i];  // (b, z, y, x)
    unsigned int b = (unsigned int)c.x & 15u;
    unsigned int wcx = (unsigned int)(c.w >> 4);
    unsigned int wcy = (unsigned int)(c.z >> 4);
    unsigned int wcz = (unsigned int)(c.y >> 3);

    unsigned int bx = (b << 14) | (wcx << 8) | (wcy << 2) | wcz;
    unsigned int by = (1u << 18) | (b << 14) | (wcy << 8) | (wcx << 2) | wcz;

    atomicAdd(&g_hist[bx], 1u);
    atomicAdd(&g_hist[by], 1u);

    win2flat[i] = (float)(i + g_bias[b]);
}

// --- Kernel S1: per-tile local exclusive scan + tile totals + hist zeroing --
__global__ void __launch_bounds__(SCAN_BLOCK)
scan_local_kernel() {
    __shared__ unsigned int s_warp[SCAN_BLOCK / 32];   // 8

    int tile = blockIdx.x;
    int t    = threadIdx.x;
    int wid  = t >> 5;
    int lane = t & 31;

    unsigned int base = (unsigned int)tile * SCAN_TILE
                      + (unsigned int)t * SCAN_ITEMS;

    uint4 a  = *reinterpret_cast<uint4*>(&g_hist[base]);
    uint4 bv = *reinterpret_cast<uint4*>(&g_hist[base + 4]);
    uint4 zz = make_uint4(0, 0, 0, 0);
    *reinterpret_cast<uint4*>(&g_hist[base])     = zz;   // self-zero for replay
    *reinterpret_cast<uint4*>(&g_hist[base + 4]) = zz;

    unsigned int v[SCAN_ITEMS] = {a.x, a.y, a.z, a.w, bv.x, bv.y, bv.z, bv.w};
    unsigned int T = 0;
    #pragma unroll
    for (int j = 0; j < SCAN_ITEMS; j++) T += v[j];

    // warp inclusive scan of T (all 32 lanes active, full mask)
    unsigned int inc = T;
    #pragma unroll
    for (int o = 1; o < 32; o <<= 1) {
        unsigned int u = __shfl_up_sync(0xffffffffu, inc, o);
        if (lane >= o) inc += u;
    }
    if (lane == 31) s_warp[wid] = inc;
    unsigned int thread_excl = inc - T;
    __syncthreads();

    // scan the 8 warp sums: ALL lanes of warp 0 execute (safe full-mask shfl)
    if (wid == 0) {
        unsigned int w  = (lane < (SCAN_BLOCK / 32)) ? s_warp[lane] : 0u;
        unsigned int wi = w;
        #pragma unroll
        for (int o = 1; o < (SCAN_BLOCK / 32); o <<= 1) {
            unsigned int u = __shfl_up_sync(0xffffffffu, wi, o);
            if (lane >= o) wi += u;
        }
        if (lane < (SCAN_BLOCK / 32)) s_warp[lane] = wi - w;  // exclusive
        if (lane == (SCAN_BLOCK / 32) - 1) g_tilesum[tile] = wi;  // block total
    }
    __syncthreads();

    unsigned int off = s_warp[wid] + thread_excl;   // LOCAL exclusive offset
    uint4 o1, o2;
    o1.x = off;  off += v[0];
    o1.y = off;  off += v[1];
    o1.z = off;  off += v[2];
    o1.w = off;  off += v[3];
    o2.x = off;  off += v[4];
    o2.y = off;  off += v[5];
    o2.z = off;  off += v[6];
    o2.w = off;
    *reinterpret_cast<uint4*>(&g_offs[base])     = o1;
    *reinterpret_cast<uint4*>(&g_offs[base + 4]) = o2;
}

// --- Kernel S2: single-block exclusive scan of 256 tile totals --------------
__global__ void __launch_bounds__(NTILES)
scan_tiles_kernel() {
    __shared__ unsigned int s_warp[NTILES / 32];   // 8

    int t    = threadIdx.x;
    int wid  = t >> 5;
    int lane = t & 31;

    unsigned int T = g_tilesum[t];
    unsigned int inc = T;
    #pragma unroll
    for (int o = 1; o < 32; o <<= 1) {
        unsigned int u = __shfl_up_sync(0xffffffffu, inc, o);
        if (lane >= o) inc += u;
    }
    if (lane == 31) s_warp[wid] = inc;
    __syncthreads();

    if (wid == 0) {
        unsigned int w  = (lane < (NTILES / 32)) ? s_warp[lane] : 0u;
        unsigned int wi = w;
        #pragma unroll
        for (int o = 1; o < (NTILES / 32); o <<= 1) {
            unsigned int u = __shfl_up_sync(0xffffffffu, wi, o);
            if (lane >= o) wi += u;
        }
        if (lane < (NTILES / 32)) s_warp[lane] = wi - w;
    }
    __syncthreads();

    g_tilebase[t] = s_warp[wid] + (inc - T);   // exclusive tile base
}

// --- Kernel C: scatter packed (ciw<<21 | i) ----------------------------------
__global__ void scatter_kernel(const int* __restrict__ coords, int n) {
    int i = blockIdx.x * blockDim.x + threadIdx.x;
    if (i >= n) return;

    int4 c = reinterpret_cast<const int4*>(coords)[i];
    unsigned int b = (unsigned int)c.x & 15u;
    unsigned int wcx = (unsigned int)(c.w >> 4), cix = (unsigned int)(c.w & 15);
    unsigned int wcy = (unsigned int)(c.z >> 4), ciy = (unsigned int)(c.z & 15);
    unsigned int wcz = (unsigned int)(c.y >> 3), ciz = (unsigned int)(c.y & 7);

    unsigned int bx = (b << 14) | (wcx << 8) | (wcy << 2) | wcz;
    unsigned int by = (1u << 18) | (b << 14) | (wcy << 8) | (wcx << 2) | wcz;

    unsigned int cwx = (cix << 7) | (ciy << 3) | ciz;
    unsigned int cwy = (ciy << 7) | (cix << 3) | ciz;

    unsigned int px = atomicAdd(&g_offs[bx], 1u) + g_tilebase[bx >> TILE_SHIFT];
    g_binned[px] = (cwx << 21) | (unsigned int)i;
    unsigned int py = atomicAdd(&g_offs[by], 1u) + g_tilebase[by >> TILE_SHIFT];
    g_binned[py] = (cwy << 21) | (unsigned int)i;
}

// --- Kernel D: per-window stable micro-sort by (ciw, i) ---------------------
#define WCAP 32
__global__ void window_sort_kernel(float* __restrict__ out) {
    int w = blockIdx.x * blockDim.x + threadIdx.x;
    if (w >= NBINS) return;

    // post-scatter: g_offs[w] = local_excl[w] + count[w]
    unsigned int end   = g_offs[w] + g_tilebase[w >> TILE_SHIFT];
    unsigned int start = (w == 0)
        ? 0u
        : g_offs[w - 1] + g_tilebase[(w - 1) >> TILE_SHIFT];
    int cnt = (int)(end - start);
    if (cnt <= 0) return;

    const unsigned int M21 = (1u << 21) - 1u;

    if (cnt == 1) {
        out[start] = (float)(g_binned[start] & M21);
        return;
    }
    if (cnt <= WCAP) {
        unsigned int v[WCAP];
        for (int j = 0; j < cnt; j++) v[j] = g_binned[start + j];
        for (int j = 1; j < cnt; j++) {               // insertion sort
            unsigned int key = v[j];
            int k = j - 1;
            while (k >= 0 && v[k] > key) { v[k + 1] = v[k]; k--; }
            v[k + 1] = key;
        }
        for (int j = 0; j < cnt; j++)
            out[start + j] = (float)(v[j] & M21);
    } else {
        for (int a = 0; a < cnt; a++) {               // rank fallback (unique)
            unsigned int va = g_binned[start + a];
            int r = 0;
            for (int q = 0; q < cnt; q++)
                r += (g_binned[start + q] < va);
            out[start + r] = (float)(va & M21);
        }
    }
}

// --- Kernel E: flat2win over padded index space ------------------------------
__global__ void flat2win_kernel(int n_p, float* __restrict__ out) {
    int k = blockIdx.x * blockDim.x + threadIdx.x;
    if (k >= n_p) return;

    int nb = g_nb;
    int b = 0;
    #pragma unroll 1
    for (int j = 1; j < nb; j++) {
        if (g_bsp[j] <= k) b = j; else break;
    }
    int bias = g_bias[b];
    int num  = g_num[b];
    int nump = g_nump[b];
    int bspb = g_bsp[b];

    bool in_tail = (num != nump) && (k >= bspb + num);
    int val;
    if (in_tail) {
        if (nump != GROUPSZ) {
            val = k - GROUPSZ - bias;
        } else {
            int m = num > 1 ? num : 1;
            val = g_bs[b] + (k - bspb - num) % m;
        }
    } else {
        val = k - bias;
    }
    out[k] = (float)val;
}

extern "C" void kernel_launch(void* const* d_in, const int* in_sizes, int n_in,
                              void* d_out, int out_size) {
    int ci = 0;
    for (int i = 1; i < n_in; i++)
        if (in_sizes[i] > in_sizes[ci]) ci = i;

    const int* coords = (const int*)d_in[ci];
    int n = in_sizes[ci] / 4;
    if (n < 1) n = 1;
    if (n > NMAX) n = NMAX;

    const int* bsz = nullptr;
    for (int i = 0; i < n_in; i++) {
        if (i == ci) continue;
        if (in_sizes[i] == 1 && !bsz) bsz = (const int*)d_in[i];
    }

    float* out = (float*)d_out;

    bool concat = (out_size >= 3 * n);
    int n_p = concat ? (out_size - 3 * n) : out_size;
    if (n_p < 0) n_p = 0;
    if (n_p > out_size) n_p = out_size;

    batch_setup_kernel<<<1, 128>>>(coords, n, bsz);

    int blocks_p = (n_p + 255) / 256;
    if (blocks_p >= 1)
        flat2win_kernel<<<blocks_p, 256>>>(n_p, out);

    if (!concat) return;

    float* w2f  = out + n_p;
    float* idxx = out + n_p + n;   // idx_x ++ idx_y contiguous (2n floats)

    int blocks = (n + 255) / 256;
    map_hist_kernel<<<blocks, 256>>>(coords, n, w2f);

    scan_local_kernel<<<NTILES, SCAN_BLOCK>>>();
    scan_tiles_kernel<<<1, NTILES>>>();

    scatter_kernel<<<blocks, 256>>>(coords, n);

    window_sort_kernel<<<NBINS / 256, 256>>>(idxx);
}

// round 9
// speedup vs baseline: 1.4243x; 1.4243x over previous
#include <cuda_runtime.h>
#include <cuda_bf16.h>

// ---------------------------------------------------------------------------
// FlattenedWindowMapping (outputs compared as float32)
// Layout: concat [flat2win[n_p] | win2flat[n] | idx_x[n] | idx_y[n]]
//
// Counting sort over (flag, batch, window) buckets (2^19 bins):
//   bucket = flag<<18 | b<<14 | wcx<<8 | wcy<<2 | wcz   (x-orientation)
//            flag<<18 | b<<14 | wcy<<8 | wcx<<2 | wcz   (y-orientation)
//   element = ciw<<21 | i        (ciw 11 bits, i < 2^21)
// then per-window stable micro-sort by (ciw, i)  == reference key order.
//
// Two-level scan (hang-proof): S1 per-tile (512 bins, 1024 blocks) local scan
// + inline hist self-zeroing for graph replay; S2 one 1024-thread block scans
// tile totals; tile base added at use sites.
// ---------------------------------------------------------------------------

#define MAXB  16
#define NMAX  2000000            // < 2^21 for packing
#define NMAX2 (2 * NMAX)
#define NBINS (1 << 19)
#define GROUPSZ 128

#define S1_BLOCK 128
#define S1_ITEMS 4
#define SCAN_TILE  (S1_BLOCK * S1_ITEMS)          // 512
#define NTILES     (NBINS / SCAN_TILE)            // 1024
#define TILE_SHIFT 9                              // log2(SCAN_TILE)

__device__ int g_nb;
__device__ int g_bs[MAXB + 1];
__device__ int g_num[MAXB];
__device__ int g_nump[MAXB];
__device__ int g_bsp[MAXB + 1];
__device__ int g_bias[MAXB];

__device__ __align__(16) unsigned int g_hist[NBINS];
__device__ __align__(16) unsigned int g_offs[NBINS];   // per-tile local offsets
__device__ unsigned int g_tilesum[NTILES];
__device__ unsigned int g_tilebase[NTILES];
__device__ unsigned int g_binned[NMAX2];

// --- Kernel A: per-batch boundaries via binary search ------------------------
__global__ void batch_setup_kernel(const int* __restrict__ coords, int n,
                                   const int* __restrict__ bsz_ptr) {
    __shared__ int nb_s;
    int t = threadIdx.x;
    if (t == 0) {
        int nb = bsz_ptr ? bsz_ptr[0] : 16;
        if (nb < 1) nb = 1;
        if (nb > MAXB) nb = MAXB;
        nb_s = nb;
        g_nb = nb;
    }
    __syncthreads();
    int nb = nb_s;
    if (t <= nb) {
        int lo = 0, hi = n;
        while (lo < hi) {
            int mid = (lo + hi) >> 1;
            if (coords[4 * mid] < t) lo = mid + 1; else hi = mid;
        }
        g_bs[t] = lo;
    }
    __syncthreads();
    if (t == 0) {
        int acc = 0;
        for (int b = 0; b < nb; b++) {
            int num  = g_bs[b + 1] - g_bs[b];
            int nump = ((num + GROUPSZ - 1) / GROUPSZ) * GROUPSZ;
            g_num[b]  = num;
            g_nump[b] = nump;
            g_bsp[b]  = acc;
            g_bias[b] = acc - g_bs[b];
            acc += nump;
        }
        g_bsp[nb] = acc;
    }
}

// --- Kernel B (fused): flat2win + win2flat + bucket histogram ---------------
__global__ void fused_map_kernel(const int* __restrict__ coords, int n,
                                 int n_p,
                                 float* __restrict__ f2w,
                                 float* __restrict__ win2flat) {
    int k = blockIdx.x * blockDim.x + threadIdx.x;

    if (k < n_p) {
        int nb = g_nb;
        int b = 0;
        #pragma unroll 1
        for (int j = 1; j < nb; j++) {
            if (g_bsp[j] <= k) b = j; else break;
        }
        int bias = g_bias[b];
        int num  = g_num[b];
        int nump = g_nump[b];
        int bspb = g_bsp[b];

        bool in_tail = (num != nump) && (k >= bspb + num);
        int val;
        if (in_tail) {
            if (nump != GROUPSZ) {
                val = k - GROUPSZ - bias;
            } else {
                int m = num > 1 ? num : 1;
                val = g_bs[b] + (k - bspb - num) % m;
            }
        } else {
            val = k - bias;
        }
        f2w[k] = (float)val;
    }

    if (k < n) {
        int4 c = reinterpret_cast<const int4*>(coords)[k];  // (b, z, y, x)
        unsigned int b = (unsigned int)c.x & 15u;
        unsigned int wcx = (unsigned int)(c.w >> 4);
        unsigned int wcy = (unsigned int)(c.z >> 4);
        unsigned int wcz = (unsigned int)(c.y >> 3);

        unsigned int bx = (b << 14) | (wcx << 8) | (wcy << 2) | wcz;
        unsigned int by = (1u << 18) | (b << 14) | (wcy << 8) | (wcx << 2) | wcz;

        atomicAdd(&g_hist[bx], 1u);
        atomicAdd(&g_hist[by], 1u);

        win2flat[k] = (float)(k + g_bias[b]);
    }
}

// --- Kernel S1: per-tile local exclusive scan (1024 blocks) + hist zeroing --
__global__ void __launch_bounds__(S1_BLOCK)
scan_local_kernel() {
    __shared__ unsigned int s_warp[S1_BLOCK / 32];   // 4

    int tile = blockIdx.x;
    int t    = threadIdx.x;
    int wid  = t >> 5;
    int lane = t & 31;

    unsigned int base = (unsigned int)tile * SCAN_TILE
                      + (unsigned int)t * S1_ITEMS;

    uint4 a = *reinterpret_cast<uint4*>(&g_hist[base]);
    *reinterpret_cast<uint4*>(&g_hist[base]) = make_uint4(0, 0, 0, 0); // replay

    unsigned int v0 = a.x, v1 = a.y, v2 = a.z, v3 = a.w;
    unsigned int T = v0 + v1 + v2 + v3;

    unsigned int inc = T;
    #pragma unroll
    for (int o = 1; o < 32; o <<= 1) {
        unsigned int u = __shfl_up_sync(0xffffffffu, inc, o);
        if (lane >= o) inc += u;
    }
    if (lane == 31) s_warp[wid] = inc;
    unsigned int thread_excl = inc - T;
    __syncthreads();

    if (wid == 0) {
        unsigned int w  = (lane < (S1_BLOCK / 32)) ? s_warp[lane] : 0u;
        unsigned int wi = w;
        #pragma unroll
        for (int o = 1; o < (S1_BLOCK / 32); o <<= 1) {
            unsigned int u = __shfl_up_sync(0xffffffffu, wi, o);
            if (lane >= o) wi += u;
        }
        if (lane < (S1_BLOCK / 32)) s_warp[lane] = wi - w;  // exclusive
        if (lane == (S1_BLOCK / 32) - 1) g_tilesum[tile] = wi;
    }
    __syncthreads();

    unsigned int off = s_warp[wid] + thread_excl;
    uint4 o1;
    o1.x = off;  off += v0;
    o1.y = off;  off += v1;
    o1.z = off;  off += v2;
    o1.w = off;
    *reinterpret_cast<uint4*>(&g_offs[base]) = o1;
}

// --- Kernel S2: single-block exclusive scan of 1024 tile totals -------------
__global__ void __launch_bounds__(NTILES)
scan_tiles_kernel() {
    __shared__ unsigned int s_warp[NTILES / 32];   // 32

    int t    = threadIdx.x;
    int wid  = t >> 5;
    int lane = t & 31;

    unsigned int T = g_tilesum[t];
    unsigned int inc = T;
    #pragma unroll
    for (int o = 1; o < 32; o <<= 1) {
        unsigned int u = __shfl_up_sync(0xffffffffu, inc, o);
        if (lane >= o) inc += u;
    }
    if (lane == 31) s_warp[wid] = inc;
    __syncthreads();

    if (wid == 0) {
        unsigned int w  = s_warp[lane];   // 32 warps -> exactly 32 lanes
        unsigned int wi = w;
        #pragma unroll
        for (int o = 1; o < 32; o <<= 1) {
            unsigned int u = __shfl_up_sync(0xffffffffu, wi, o);
            if (lane >= o) wi += u;
        }
        s_warp[lane] = wi - w;
    }
    __syncthreads();

    g_tilebase[t] = s_warp[wid] + (inc - T);
}

// --- Kernel C: scatter packed (ciw<<21 | i) ----------------------------------
__global__ void scatter_kernel(const int* __restrict__ coords, int n) {
    int i = blockIdx.x * blockDim.x + threadIdx.x;
    if (i >= n) return;

    int4 c = reinterpret_cast<const int4*>(coords)[i];
    unsigned int b = (unsigned int)c.x & 15u;
    unsigned int wcx = (unsigned int)(c.w >> 4), cix = (unsigned int)(c.w & 15);
    unsigned int wcy = (unsigned int)(c.z >> 4), ciy = (unsigned int)(c.z & 15);
    unsigned int wcz = (unsigned int)(c.y >> 3), ciz = (unsigned int)(c.y & 7);

    unsigned int bx = (b << 14) | (wcx << 8) | (wcy << 2) | wcz;
    unsigned int by = (1u << 18) | (b << 14) | (wcy << 8) | (wcx << 2) | wcz;

    unsigned int cwx = (cix << 7) | (ciy << 3) | ciz;
    unsigned int cwy = (ciy << 7) | (cix << 3) | ciz;

    unsigned int px = atomicAdd(&g_offs[bx], 1u) + g_tilebase[bx >> TILE_SHIFT];
    g_binned[px] = (cwx << 21) | (unsigned int)i;
    unsigned int py = atomicAdd(&g_offs[by], 1u) + g_tilebase[by >> TILE_SHIFT];
    g_binned[py] = (cwy << 21) | (unsigned int)i;
}

// --- Kernel D: per-window stable micro-sort by (ciw, i) ---------------------
#define WCAP 16
__global__ void window_sort_kernel(float* __restrict__ out) {
    int w = blockIdx.x * blockDim.x + threadIdx.x;
    if (w >= NBINS) return;

    unsigned int end   = g_offs[w] + g_tilebase[w >> TILE_SHIFT];
    unsigned int start = (w == 0)
        ? 0u
        : g_offs[w - 1] + g_tilebase[(w - 1) >> TILE_SHIFT];
    int cnt = (int)(end - start);
    if (cnt <= 0) return;

    const unsigned int M21 = (1u << 21) - 1u;

    if (cnt == 1) {
        out[start] = (float)(g_binned[start] & M21);
        return;
    }
    if (cnt <= WCAP) {
        unsigned int v[WCAP];
        for (int j = 0; j < cnt; j++) v[j] = g_binned[start + j];
        for (int j = 1; j < cnt; j++) {               // insertion sort
            unsigned int key = v[j];
            int k = j - 1;
            while (k >= 0 && v[k] > key) { v[k + 1] = v[k]; k--; }
            v[k + 1] = key;
        }
        for (int j = 0; j < cnt; j++)
            out[start + j] = (float)(v[j] & M21);
    } else {
        for (int a = 0; a < cnt; a++) {               // rank method (unique)
            unsigned int va = g_binned[start + a];
            int r = 0;
            for (int q = 0; q < cnt; q++)
                r += (g_binned[start + q] < va);
            out[start + r] = (float)(va & M21);
        }
    }
}

extern "C" void kernel_launch(void* const* d_in, const int* in_sizes, int n_in,
                              void* d_out, int out_size) {
    int ci = 0;
    for (int i = 1; i < n_in; i++)
        if (in_sizes[i] > in_sizes[ci]) ci = i;

    const int* coords = (const int*)d_in[ci];
    int n = in_sizes[ci] / 4;
    if (n < 1) n = 1;
    if (n > NMAX) n = NMAX;

    const int* bsz = nullptr;
    for (int i = 0; i < n_in; i++) {
        if (i == ci) continue;
        if (in_sizes[i] == 1 && !bsz) bsz = (const int*)d_in[i];
    }

    float* out = (float*)d_out;

    bool concat = (out_size >= 3 * n);
    int n_p = concat ? (out_size - 3 * n) : out_size;
    if (n_p < 0) n_p = 0;
    if (n_p > out_size) n_p = out_size;

    batch_setup_kernel<<<1, 128>>>(coords, n, bsz);

    if (!concat) {
        // single-output mode: flat2win only (pass n = 0 region for map part)
        int blocks_p = (n_p + 255) / 256;
        if (blocks_p >= 1)
            fused_map_kernel<<<blocks_p, 256>>>(coords, 0, n_p, out, out);
        return;
    }

    float* w2f  = out + n_p;
    float* idxx = out + n_p + n;   // idx_x ++ idx_y contiguous (2n floats)

    int m = (n_p > n) ? n_p : n;
    int blocks_m = (m + 255) / 256;
    fused_map_kernel<<<blocks_m, 256>>>(coords, n, n_p, out, w2f);

    scan_local_kernel<<<NTILES, S1_BLOCK>>>();
    scan_tiles_kernel<<<1, NTILES>>>();

    int blocks = (n + 255) / 256;
    scatter_kernel<<<blocks, 256>>>(coords, n);

    window_sort_kernel<<<NBINS / 256, 256>>>(idxx);
}

// round 10
// speedup vs baseline: 1.4566x; 1.0227x over previous
#include <cuda_runtime.h>
#include <cuda_bf16.h>

// ---------------------------------------------------------------------------
// FlattenedWindowMapping (outputs compared as float32)
// Layout: concat [flat2win[n_p] | win2flat[n] | idx_x[n] | idx_y[n]]
//
// Counting sort over (flag, batch, window) buckets (2^19 bins):
//   bucket = flag<<18 | b<<14 | wcx<<8 | wcy<<2 | wcz   (x-orientation)
//            flag<<18 | b<<14 | wcy<<8 | wcx<<2 | wcz   (y-orientation)
//   element = ciw<<21 | i        (ciw 11 bits, i < 2^21)
// then per-window stable micro-sort by (ciw, i)  == reference key order.
//
// 5-kernel chain: hist -> scan_local(+batch_setup piggyback) -> scan_tiles
//   -> fused_emit (flat2win + win2flat + scatter; ONE coords read)
//   -> window_sort.
// hist self-zeroed in scan_local for graph replay.
// ---------------------------------------------------------------------------

#define MAXB  16
#define NMAX  2000000            // < 2^21 for packing
#define NMAX2 (2 * NMAX)
#define NBINS (1 << 19)
#define GROUPSZ 128

#define S1_BLOCK 128
#define S1_ITEMS 4
#define SCAN_TILE  (S1_BLOCK * S1_ITEMS)          // 512
#define NTILES     (NBINS / SCAN_TILE)            // 1024
#define TILE_SHIFT 9                              // log2(SCAN_TILE)

__device__ int g_nb;
__device__ int g_bs[MAXB + 1];
__device__ int g_num[MAXB];
__device__ int g_nump[MAXB];
__device__ int g_bsp[MAXB + 1];
__device__ int g_bias[MAXB];

__device__ __align__(16) unsigned int g_hist[NBINS];
__device__ __align__(16) unsigned int g_offs[NBINS];   // per-tile local offsets
__device__ unsigned int g_tilesum[NTILES];
__device__ unsigned int g_tilebase[NTILES];
__device__ unsigned int g_binned[NMAX2];

// --- Kernel 1: bucket histogram only (no dependencies) -----------------------
__global__ void hist_kernel(const int* __restrict__ coords, int n) {
    int i = blockIdx.x * blockDim.x + threadIdx.x;
    if (i >= n) return;

    int4 c = reinterpret_cast<const int4*>(coords)[i];  // (b, z, y, x)
    unsigned int b = (unsigned int)c.x & 15u;
    unsigned int wcx = (unsigned int)(c.w >> 4);
    unsigned int wcy = (unsigned int)(c.z >> 4);
    unsigned int wcz = (unsigned int)(c.y >> 3);

    unsigned int bx = (b << 14) | (wcx << 8) | (wcy << 2) | wcz;
    unsigned int by = (1u << 18) | (b << 14) | (wcy << 8) | (wcx << 2) | wcz;

    atomicAdd(&g_hist[bx], 1u);
    atomicAdd(&g_hist[by], 1u);
}

// --- Kernel 2: per-tile local scan + hist zeroing; block 0 also batch_setup --
__global__ void __launch_bounds__(S1_BLOCK)
scan_local_kernel(const int* __restrict__ coords, int n,
                  const int* __restrict__ bsz_ptr) {
    __shared__ unsigned int s_warp[S1_BLOCK / 32];   // 4
    __shared__ int nb_s;

    int tile = blockIdx.x;
    int t    = threadIdx.x;
    int wid  = t >> 5;
    int lane = t & 31;

    // --- piggybacked batch setup (block 0 only; overlaps other blocks) ---
    if (tile == 0) {
        if (t == 0) {
            int nb = bsz_ptr ? bsz_ptr[0] : 16;
            if (nb < 1) nb = 1;
            if (nb > MAXB) nb = MAXB;
            nb_s = nb;
            g_nb = nb;
        }
        __syncthreads();
        int nb = nb_s;
        if (t <= nb) {
            int lo = 0, hi = n;
            while (lo < hi) {
                int mid = (lo + hi) >> 1;
                if (coords[4 * mid] < t) lo = mid + 1; else hi = mid;
            }
            g_bs[t] = lo;
        }
        __syncthreads();
        if (t == 0) {
            int acc = 0;
            for (int b = 0; b < nb; b++) {
                int num  = g_bs[b + 1] - g_bs[b];
                int nump = ((num + GROUPSZ - 1) / GROUPSZ) * GROUPSZ;
                g_num[b]  = num;
                g_nump[b] = nump;
                g_bsp[b]  = acc;
                g_bias[b] = acc - g_bs[b];
                acc += nump;
            }
            g_bsp[nb] = acc;
        }
        __syncthreads();
    }

    // --- per-tile scan ---
    unsigned int base = (unsigned int)tile * SCAN_TILE
                      + (unsigned int)t * S1_ITEMS;

    uint4 a = *reinterpret_cast<uint4*>(&g_hist[base]);
    *reinterpret_cast<uint4*>(&g_hist[base]) = make_uint4(0, 0, 0, 0); // replay

    unsigned int v0 = a.x, v1 = a.y, v2 = a.z, v3 = a.w;
    unsigned int T = v0 + v1 + v2 + v3;

    unsigned int inc = T;
    #pragma unroll
    for (int o = 1; o < 32; o <<= 1) {
        unsigned int u = __shfl_up_sync(0xffffffffu, inc, o);
        if (lane >= o) inc += u;
    }
    if (lane == 31) s_warp[wid] = inc;
    unsigned int thread_excl = inc - T;
    __syncthreads();

    if (wid == 0) {
        unsigned int w  = (lane < (S1_BLOCK / 32)) ? s_warp[lane] : 0u;
        unsigned int wi = w;
        #pragma unroll
        for (int o = 1; o < (S1_BLOCK / 32); o <<= 1) {
            unsigned int u = __shfl_up_sync(0xffffffffu, wi, o);
            if (lane >= o) wi += u;
        }
        if (lane < (S1_BLOCK / 32)) s_warp[lane] = wi - w;  // exclusive
        if (lane == (S1_BLOCK / 32) - 1) g_tilesum[tile] = wi;
    }
    __syncthreads();

    unsigned int off = s_warp[wid] + thread_excl;
    uint4 o1;
    o1.x = off;  off += v0;
    o1.y = off;  off += v1;
    o1.z = off;  off += v2;
    o1.w = off;
    *reinterpret_cast<uint4*>(&g_offs[base]) = o1;
}

// --- Kernel 3: single-block exclusive scan of 1024 tile totals --------------
__global__ void __launch_bounds__(NTILES)
scan_tiles_kernel() {
    __shared__ unsigned int s_warp[NTILES / 32];   // 32

    int t    = threadIdx.x;
    int wid  = t >> 5;
    int lane = t & 31;

    unsigned int T = g_tilesum[t];
    unsigned int inc = T;
    #pragma unroll
    for (int o = 1; o < 32; o <<= 1) {
        unsigned int u = __shfl_up_sync(0xffffffffu, inc, o);
        if (lane >= o) inc += u;
    }
    if (lane == 31) s_warp[wid] = inc;
    __syncthreads();

    if (wid == 0) {
        unsigned int w  = s_warp[lane];
        unsigned int wi = w;
        #pragma unroll
        for (int o = 1; o < 32; o <<= 1) {
            unsigned int u = __shfl_up_sync(0xffffffffu, wi, o);
            if (lane >= o) wi += u;
        }
        s_warp[lane] = wi - w;
    }
    __syncthreads();

    g_tilebase[t] = s_warp[wid] + (inc - T);
}

// --- Kernel 4 (fused): flat2win + win2flat + scatter (single coords read) ---
__global__ void fused_emit_kernel(const int* __restrict__ coords, int n,
                                  int n_p,
                                  float* __restrict__ f2w,
                                  float* __restrict__ win2flat) {
    int k = blockIdx.x * blockDim.x + threadIdx.x;

    if (k < n_p) {
        int nb = g_nb;
        int b = 0;
        #pragma unroll 1
        for (int j = 1; j < nb; j++) {
            if (g_bsp[j] <= k) b = j; else break;
        }
        int bias = g_bias[b];
        int num  = g_num[b];
        int nump = g_nump[b];
        int bspb = g_bsp[b];

        bool in_tail = (num != nump) && (k >= bspb + num);
        int val;
        if (in_tail) {
            if (nump != GROUPSZ) {
                val = k - GROUPSZ - bias;
            } else {
                int m = num > 1 ? num : 1;
                val = g_bs[b] + (k - bspb - num) % m;
            }
        } else {
            val = k - bias;
        }
        f2w[k] = (float)val;
    }

    if (k < n) {
        int4 c = reinterpret_cast<const int4*>(coords)[k];  // (b, z, y, x)
        unsigned int b = (unsigned int)c.x & 15u;
        unsigned int wcx = (unsigned int)(c.w >> 4), cix = (unsigned int)(c.w & 15);
        unsigned int wcy = (unsigned int)(c.z >> 4), ciy = (unsigned int)(c.z & 15);
        unsigned int wcz = (unsigned int)(c.y >> 3), ciz = (unsigned int)(c.y & 7);

        win2flat[k] = (float)(k + g_bias[b]);

        unsigned int bx = (b << 14) | (wcx << 8) | (wcy << 2) | wcz;
        unsigned int by = (1u << 18) | (b << 14) | (wcy << 8) | (wcx << 2) | wcz;

        unsigned int cwx = (cix << 7) | (ciy << 3) | ciz;
        unsigned int cwy = (ciy << 7) | (cix << 3) | ciz;

        unsigned int px = atomicAdd(&g_offs[bx], 1u) + g_tilebase[bx >> TILE_SHIFT];
        g_binned[px] = (cwx << 21) | (unsigned int)k;
        unsigned int py = atomicAdd(&g_offs[by], 1u) + g_tilebase[by >> TILE_SHIFT];
        g_binned[py] = (cwy << 21) | (unsigned int)k;
    }
}

// --- Kernel 5: per-window stable micro-sort by (ciw, i) ---------------------
#define WCAP 16
__global__ void window_sort_kernel(float* __restrict__ out) {
    int w = blockIdx.x * blockDim.x + threadIdx.x;
    if (w >= NBINS) return;

    unsigned int end   = g_offs[w] + g_tilebase[w >> TILE_SHIFT];
    unsigned int start = (w == 0)
        ? 0u
        : g_offs[w - 1] + g_tilebase[(w - 1) >> TILE_SHIFT];
    int cnt = (int)(end - start);
    if (cnt <= 0) return;

    const unsigned int M21 = (1u << 21) - 1u;

    if (cnt == 1) {
        out[start] = (float)(g_binned[start] & M21);
        return;
    }
    if (cnt <= WCAP) {
        unsigned int v[WCAP];
        for (int j = 0; j < cnt; j++) v[j] = g_binned[start + j];
        for (int j = 1; j < cnt; j++) {               // insertion sort
            unsigned int key = v[j];
            int k = j - 1;
            while (k >= 0 && v[k] > key) { v[k + 1] = v[k]; k--; }
            v[k + 1] = key;
        }
        for (int j = 0; j < cnt; j++)
            out[start + j] = (float)(v[j] & M21);
    } else {
        for (int a = 0; a < cnt; a++) {               // rank method (unique)
            unsigned int va = g_binned[start + a];
            int r = 0;
            for (int q = 0; q < cnt; q++)
                r += (g_binned[start + q] < va);
            out[start + r] = (float)(va & M21);
        }
    }
}

extern "C" void kernel_launch(void* const* d_in, const int* in_sizes, int n_in,
                              void* d_out, int out_size) {
    int ci = 0;
    for (int i = 1; i < n_in; i++)
        if (in_sizes[i] > in_sizes[ci]) ci = i;

    const int* coords = (const int*)d_in[ci];
    int n = in_sizes[ci] / 4;
    if (n < 1) n = 1;
    if (n > NMAX) n = NMAX;

    const int* bsz = nullptr;
    for (int i = 0; i < n_in; i++) {
        if (i == ci) continue;
        if (in_sizes[i] == 1 && !bsz) bsz = (const int*)d_in[i];
    }

    float* out = (float*)d_out;

    bool concat = (out_size >= 3 * n);
    int n_p = concat ? (out_size - 3 * n) : out_size;
    if (n_p < 0) n_p = 0;
    if (n_p > out_size) n_p = out_size;

    if (!concat) {
        // single-output mode: batch setup (in scan block 0) + flat2win only
        scan_local_kernel<<<NTILES, S1_BLOCK>>>(coords, n, bsz);
        int blocks_p = (n_p + 255) / 256;
        if (blocks_p >= 1)
            fused_emit_kernel<<<blocks_p, 256>>>(coords, 0, n_p, out, out);
        return;
    }

    float* w2f  = out + n_p;
    float* idxx = out + n_p + n;   // idx_x ++ idx_y contiguous (2n floats)

    int blocks = (n + 255) / 256;
    hist_kernel<<<blocks, 256>>>(coords, n);

    scan_local_kernel<<<NTILES, S1_BLOCK>>>(coords, n, bsz);
    scan_tiles_kernel<<<1, NTILES>>>();

    int m = (n_p > n) ? n_p : n;
    int blocks_m = (m + 255) / 256;
    fused_emit_kernel<<<blocks_m, 256>>>(coords, n, n_p, out, w2f);

    window_sort_kernel<<<NBINS / 256, 256>>>(idxx);
}